// round 2
// baseline (speedup 1.0000x reference)
#include <cuda_runtime.h>
#include <stdint.h>

#define N_NODES 100000
#define N_EDGES 3200000
#define F_IN    256
#define HID     64
#define NCLS    16

// ---------------- device scratch (no allocations allowed) ----------------
__device__ int   g_off_src[N_NODES + 1];
__device__ int   g_off_dst[N_NODES + 1];
__device__ int   g_cur_src[N_NODES];
__device__ int   g_cur_dst[N_NODES];
__device__ float g_es_t[N_EDGES];          // t sorted by src segment
__device__ float2 g_ed_ts[N_EDGES];        // (t, src) sorted by dst segment
__device__ float g_x1[(size_t)N_NODES * HID];
__device__ float g_y1[(size_t)N_NODES * HID];
__device__ float g_h1[(size_t)N_NODES * HID];
__device__ float g_x2[(size_t)N_NODES * NCLS];
__device__ float g_y2[(size_t)N_NODES * NCLS];
__device__ float g_Wt1[F_IN * HID];
__device__ float g_Wt2[HID * NCLS];
__device__ float g_Apos1[HID], g_Aneg1[HID], g_Mk1[HID];
__device__ float g_Apos2[NCLS], g_Aneg2[NCLS], g_Mk2[NCLS];
__device__ unsigned g_text[4];             // encoded tpmax, tpmin, tnmax, tnmin
__device__ int   g_is64;                   // 1 if edge_index stored as int64

// monotonic float<->uint encoding for atomic min/max on floats
__device__ __forceinline__ unsigned fenc(float f) {
    unsigned u = __float_as_uint(f);
    return (u & 0x80000000u) ? ~u : (u | 0x80000000u);
}
__device__ __forceinline__ float fdec(unsigned u) {
    u = (u & 0x80000000u) ? (u & 0x7fffffffu) : ~u;
    return __uint_as_float(u);
}

// edge loader: handles int32 or int64 storage (flag in g_is64)
__device__ __forceinline__ void load_edge(const int* __restrict__ ei32, int is64, int e,
                                          int& s, int& d) {
    if (is64) {
        const long long* ei64 = (const long long*)ei32;
        s = (int)ei64[e];
        d = (int)ei64[N_EDGES + e];
    } else {
        s = ei32[e];
        d = ei32[N_EDGES + e];
    }
}

// ---------------- setup kernels ----------------
// Detect dtype: for int64 data with values < 2^31, all high words are 0.
// For int32 data, odd int32 positions are random node ids (not all zero).
__global__ void k_detect(const int* __restrict__ ei32) {
    int v = ei32[2 * threadIdx.x + 1];
    int anynz = __syncthreads_or(v != 0);
    if (threadIdx.x == 0) g_is64 = (anynz == 0) ? 1 : 0;
}

__global__ void k_init() {
    int i = blockIdx.x * blockDim.x + threadIdx.x;
    int stride = gridDim.x * blockDim.x;
    for (int j = i; j < N_NODES; j += stride) { g_cur_src[j] = 0; g_cur_dst[j] = 0; }
    if (i == 0) {
        g_text[0] = fenc(-1e30f); g_text[1] = fenc(1e30f);
        g_text[2] = fenc(-1e30f); g_text[3] = fenc(1e30f);
    }
}

__global__ void k_hist(const int* __restrict__ ei32, const float* __restrict__ wm) {
    int i0 = blockIdx.x * blockDim.x + threadIdx.x;
    int stride = gridDim.x * blockDim.x;
    int is64 = g_is64;
    float tpmax = -1e30f, tpmin = 1e30f, tnmax = -1e30f, tnmin = 1e30f;
    for (int e = i0; e < N_EDGES; e += stride) {
        int s, d;
        load_edge(ei32, is64, e, s, d);
        atomicAdd(&g_cur_src[s], 1);
        atomicAdd(&g_cur_dst[d], 1);
        float t = wm[e];
        if (t >= 0.f) { tpmax = fmaxf(tpmax, t); tpmin = fminf(tpmin, t); }
        else          { tnmax = fmaxf(tnmax, t); tnmin = fminf(tnmin, t); }
    }
    for (int o = 16; o; o >>= 1) {
        tpmax = fmaxf(tpmax, __shfl_xor_sync(0xffffffffu, tpmax, o));
        tpmin = fminf(tpmin, __shfl_xor_sync(0xffffffffu, tpmin, o));
        tnmax = fmaxf(tnmax, __shfl_xor_sync(0xffffffffu, tnmax, o));
        tnmin = fminf(tnmin, __shfl_xor_sync(0xffffffffu, tnmin, o));
    }
    if ((threadIdx.x & 31) == 0) {
        atomicMax(&g_text[0], fenc(tpmax)); atomicMin(&g_text[1], fenc(tpmin));
        atomicMax(&g_text[2], fenc(tnmax)); atomicMin(&g_text[3], fenc(tnmin));
    }
}

__device__ void scan_phase(int* cnt, int* off, int* sums) {
    const int CH = (N_NODES + 1023) / 1024;
    int tid = threadIdx.x;
    int base = tid * CH;
    int lim = base + CH; if (lim > N_NODES) lim = N_NODES;
    int s = 0;
    for (int i = base; i < lim; i++) s += cnt[i];
    sums[tid] = s;
    __syncthreads();
    for (int d = 1; d < 1024; d <<= 1) {
        int v = (tid >= d) ? sums[tid - d] : 0;
        __syncthreads();
        sums[tid] += v;
        __syncthreads();
    }
    int run = sums[tid] - s;   // exclusive prefix of this chunk
    for (int i = base; i < lim; i++) {
        int c = cnt[i];
        off[i] = run;
        cnt[i] = run;          // cur[] := start offsets for scatter
        run += c;
    }
    if (tid == 1023) off[N_NODES] = run;
    __syncthreads();
}

__global__ void k_scan() {
    __shared__ int sums[1024];
    scan_phase(g_cur_src, g_off_src, sums);
    scan_phase(g_cur_dst, g_off_dst, sums);
}

__global__ void k_scatter(const int* __restrict__ ei32, const float* __restrict__ wm) {
    int i0 = blockIdx.x * blockDim.x + threadIdx.x;
    int stride = gridDim.x * blockDim.x;
    int is64 = g_is64;
    for (int e = i0; e < N_EDGES; e += stride) {
        int s, d;
        load_edge(ei32, is64, e, s, d);
        float t = wm[e];
        int p = atomicAdd(&g_cur_src[s], 1);
        g_es_t[p] = t;
        int q = atomicAdd(&g_cur_dst[d], 1);
        g_ed_ts[q] = make_float2(t, __int_as_float(s));
    }
}

__global__ void k_transpose1(const float* __restrict__ W) {
    int idx = blockIdx.x * blockDim.x + threadIdx.x;
    if (idx < F_IN * HID) { int k = idx / F_IN, f = idx % F_IN; g_Wt1[f * HID + k] = W[idx]; }
}
__global__ void k_transpose2(const float* __restrict__ W) {
    int idx = blockIdx.x * blockDim.x + threadIdx.x;
    if (idx < HID * NCLS) { int k = idx / HID, f = idx % HID; g_Wt2[f * NCLS + k] = W[idx]; }
}

// Apos[k] = sum_j max(w1_j, 0.2 w1_j) * w2[k,j]   (coefficient for t >= 0)
// Aneg[k] = sum_j min(w1_j, 0.2 w1_j) * w2[k,j]   (coefficient for t <  0)
// Mk[k]   = global max over edges of t * c_k(t)   (b2 cancels in softmax)
__device__ void prep_body(const float* __restrict__ w1, const float* __restrict__ w2,
                          int K, int Hd, float* Apos, float* Aneg, float* Mk) {
    int k = threadIdx.x;
    if (k >= K) return;
    float ap = 0.f, an = 0.f;
    for (int j = 0; j < Hd; j++) {
        float w = w1[j];
        float a = fmaxf(w, 0.2f * w);
        float b = fminf(w, 0.2f * w);
        float v = w2[k * Hd + j];
        ap = fmaf(a, v, ap);
        an = fmaf(b, v, an);
    }
    Apos[k] = ap; Aneg[k] = an;
    float tpmax = fdec(g_text[0]), tpmin = fdec(g_text[1]);
    float tnmax = fdec(g_text[2]), tnmin = fdec(g_text[3]);
    float m = -1e30f;
    if (tpmax > -1e29f) m = fmaxf(m, (ap >= 0.f ? tpmax : tpmin) * ap);
    if (tnmin <  1e29f) m = fmaxf(m, (an >= 0.f ? tnmax : tnmin) * an);
    if (m < -1e29f) m = 0.f;
    Mk[k] = m;
}
__global__ void k_prep1(const float* w1, const float* w2) { prep_body(w1, w2, HID, HID, g_Apos1, g_Aneg1, g_Mk1); }
__global__ void k_prep2(const float* w1, const float* w2) { prep_body(w1, w2, NCLS, NCLS, g_Apos2, g_Aneg2, g_Mk2); }

// ---------------- GEMM: out[n,k] = sum_i x[n,i] * W[k,i] + b[k] ----------------
template <int F, int K, int KREP>
__device__ void gemm_body(const float* __restrict__ x, const float* __restrict__ Wt,
                          const float* __restrict__ bias, float* __restrict__ out) {
    const int NPB = 8;
    const int NB = NPB * KREP;                 // nodes per block
    __shared__ __align__(16) float xs[NB * F]; // [grp][i][j] = x[node0+grp*NPB+j, i]
    int tid = threadIdx.x;                     // blockDim = K*KREP = 128
    int node0 = blockIdx.x * NB;
    for (int idx = tid; idx < NB * F; idx += K * KREP) {
        int nl = idx / F, i = idx % F;
        int node = node0 + nl;
        float v = (node < N_NODES) ? x[(size_t)node * F + i] : 0.f;
        int g2 = nl / NPB, j = nl % NPB;
        xs[(g2 * F + i) * NPB + j] = v;
    }
    __syncthreads();
    int k = tid % K, grp = tid / K;
    const float4* xs4 = (const float4*)(xs) + (size_t)grp * F * 2;
    float acc[8] = {0, 0, 0, 0, 0, 0, 0, 0};
#pragma unroll 4
    for (int i = 0; i < F; i++) {
        float w = __ldg(&Wt[i * K + k]);
        float4 a = xs4[2 * i], b = xs4[2 * i + 1];
        acc[0] = fmaf(a.x, w, acc[0]); acc[1] = fmaf(a.y, w, acc[1]);
        acc[2] = fmaf(a.z, w, acc[2]); acc[3] = fmaf(a.w, w, acc[3]);
        acc[4] = fmaf(b.x, w, acc[4]); acc[5] = fmaf(b.y, w, acc[5]);
        acc[6] = fmaf(b.z, w, acc[6]); acc[7] = fmaf(b.w, w, acc[7]);
    }
    float bb = __ldg(&bias[k]);
#pragma unroll
    for (int j = 0; j < 8; j++) {
        int node = node0 + grp * NPB + j;
        if (node < N_NODES) out[(size_t)node * K + k] = acc[j] + bb;
    }
}
__global__ void k_gemm1(const float* __restrict__ x, const float* __restrict__ b) {
    gemm_body<F_IN, HID, 2>(x, g_Wt1, b, g_x1);
}
__global__ void k_gemm2(const float* __restrict__ b) {
    gemm_body<HID, NCLS, 8>(g_h1, g_Wt2, b, g_x2);
}

// ---------------- src pass: softmax denominator folded into y = x1/S ----------------
template <int K>
__device__ void kc_body(const float* __restrict__ x1, const float* __restrict__ Apos,
                        const float* __restrict__ Aneg, const float* __restrict__ Mk,
                        float* __restrict__ y) {
    const int NPB = 128 / K;
    int tid = threadIdx.x;
    int node = blockIdx.x * NPB + tid / K;
    int k = tid % K;
    if (node >= N_NODES) return;
    int a = g_off_src[node], b = g_off_src[node + 1];
    float Ap = Apos[k], An = Aneg[k], M = Mk[k];
    float S = 0.f;
    for (int e = a; e < b; e++) {
        float t = __ldg(&g_es_t[e]);
        float c = (t >= 0.f) ? Ap : An;
        S += __expf(fmaf(t, c, -M));
    }
    y[(size_t)node * K + k] = x1[(size_t)node * K + k] / (S + 1e-16f);
}
__global__ void k_kc1() { kc_body<HID>(g_x1, g_Apos1, g_Aneg1, g_Mk1, g_y1); }
__global__ void k_kc2() { kc_body<NCLS>(g_x2, g_Apos2, g_Aneg2, g_Mk2, g_y2); }

// ---------------- dst pass: out[v,k] = sum_{e: dst=v} exp(t*c_k - Mk) * y[src,k] ----------------
template <int K, int MODE>  // MODE 0: ELU, MODE 1: log_softmax over K=16 lanes
__device__ void kd_body(const float* __restrict__ y, const float* __restrict__ Apos,
                        const float* __restrict__ Aneg, const float* __restrict__ Mk,
                        float* __restrict__ out) {
    const int NPB = 128 / K;
    int tid = threadIdx.x;
    int node = blockIdx.x * NPB + tid / K;
    int k = tid % K;
    if (node >= N_NODES) return;
    int a = g_off_dst[node], b = g_off_dst[node + 1];
    float Ap = Apos[k], An = Aneg[k], M = Mk[k];
    float acc = 0.f;
    for (int e = a; e < b; e++) {
        float2 ts = __ldg(&g_ed_ts[e]);
        float t = ts.x;
        int s = __float_as_int(ts.y);
        float c = (t >= 0.f) ? Ap : An;
        float yv = __ldg(&y[(size_t)s * K + k]);
        acc = fmaf(__expf(fmaf(t, c, -M)), yv, acc);
    }
    if (MODE == 0) {
        out[(size_t)node * K + k] = (acc > 0.f) ? acc : expm1f(acc);
    } else {
        float m = acc;
        for (int o = 8; o; o >>= 1) m = fmaxf(m, __shfl_xor_sync(0xffffffffu, m, o, 16));
        float es = __expf(acc - m);
        float ssum = es;
        for (int o = 8; o; o >>= 1) ssum += __shfl_xor_sync(0xffffffffu, ssum, o, 16);
        out[(size_t)node * K + k] = acc - m - __logf(ssum);
    }
}
__global__ void k_kd1() { kd_body<HID, 0>(g_y1, g_Apos1, g_Aneg1, g_Mk1, g_h1); }
__global__ void k_kd2(float* __restrict__ out) { kd_body<NCLS, 1>(g_y2, g_Apos2, g_Aneg2, g_Mk2, out); }

// ---------------- launch ----------------
extern "C" void kernel_launch(void* const* d_in, const int* in_sizes, int n_in,
                              void* d_out, int out_size) {
    const float* x      = (const float*)d_in[0];
    const int*   ei32   = (const int*)d_in[1];   // int32 or int64 (detected on device)
    const float* wm     = (const float*)d_in[2];
    const float* lin1_w = (const float*)d_in[3];
    const float* lin1_b = (const float*)d_in[4];
    const float* m1w1   = (const float*)d_in[5];
    const float* m1w2   = (const float*)d_in[6];
    // d_in[7] = mlp1_b2 cancels in softmax
    const float* lin2_w = (const float*)d_in[8];
    const float* lin2_b = (const float*)d_in[9];
    const float* m2w1   = (const float*)d_in[10];
    const float* m2w2   = (const float*)d_in[11];
    // d_in[12] = mlp2_b2 cancels in softmax
    float* out = (float*)d_out;

    k_detect<<<1, 512>>>(ei32);
    k_init<<<400, 256>>>();
    k_hist<<<2048, 256>>>(ei32, wm);
    k_scan<<<1, 1024>>>();
    k_scatter<<<2048, 256>>>(ei32, wm);
    k_transpose1<<<(F_IN * HID + 255) / 256, 256>>>(lin1_w);
    k_transpose2<<<(HID * NCLS + 255) / 256, 256>>>(lin2_w);
    k_prep1<<<1, HID>>>(m1w1, m1w2);
    k_prep2<<<1, NCLS>>>(m2w1, m2w2);

    // layer 1
    k_gemm1<<<(N_NODES + 15) / 16, 128>>>(x, lin1_b);
    k_kc1<<<(N_NODES + 1) / 2, 128>>>();
    k_kd1<<<(N_NODES + 1) / 2, 128>>>();

    // layer 2
    k_gemm2<<<(N_NODES + 63) / 64, 128>>>(lin2_b);
    k_kc2<<<(N_NODES + 7) / 8, 128>>>();
    k_kd2<<<(N_NODES + 7) / 8, 128>>>(out);
}

// round 3
// speedup vs baseline: 1.4474x; 1.4474x over previous
#include <cuda_runtime.h>
#include <stdint.h>

#define N_NODES 100000
#define N_EDGES 3200000
#define F_IN    256
#define HID     64
#define NCLS    16

#define SCAN_TPB 512
#define SCAN_BPA ((N_NODES + SCAN_TPB - 1) / SCAN_TPB)   // 196 blocks per array
#define SCAN_GRID (2 * SCAN_BPA)                          // 392

// ---------------- device scratch (no allocations allowed) ----------------
__device__ int   g_off_src[N_NODES + 1];
__device__ int   g_off_dst[N_NODES + 1];
__device__ int   g_cur_src[N_NODES];
__device__ int   g_cur_dst[N_NODES];
__device__ int   g_part[SCAN_GRID];
__device__ float g_es_t[N_EDGES];          // t sorted by src segment
__device__ float2 g_ed_ts[N_EDGES];        // (t, src) sorted by dst segment
__device__ float g_x1[(size_t)N_NODES * HID];
__device__ float g_y1[(size_t)N_NODES * HID];
__device__ float g_h1[(size_t)N_NODES * HID];
__device__ float g_x2[(size_t)N_NODES * NCLS];
__device__ float g_y2[(size_t)N_NODES * NCLS];
__device__ float g_Wt1[F_IN * HID];
__device__ float g_Wt2[HID * NCLS];
__device__ float g_Apos1[HID], g_Aneg1[HID], g_Mk1[HID];
__device__ float g_Apos2[NCLS], g_Aneg2[NCLS], g_Mk2[NCLS];
__device__ unsigned g_text[4];             // encoded tpmax, tpmin, tnmax, tnmin
__device__ int   g_is64;                   // 1 if edge_index stored as int64

// monotonic float<->uint encoding for atomic min/max on floats
__device__ __forceinline__ unsigned fenc(float f) {
    unsigned u = __float_as_uint(f);
    return (u & 0x80000000u) ? ~u : (u | 0x80000000u);
}
__device__ __forceinline__ float fdec(unsigned u) {
    u = (u & 0x80000000u) ? (u & 0x7fffffffu) : ~u;
    return __uint_as_float(u);
}

__device__ __forceinline__ void load_edge(const int* __restrict__ ei32, int is64, int e,
                                          int& s, int& d) {
    if (is64) {
        const long long* ei64 = (const long long*)ei32;
        s = (int)ei64[e];
        d = (int)ei64[N_EDGES + e];
    } else {
        s = ei32[e];
        d = ei32[N_EDGES + e];
    }
}

// ---------------- setup kernels ----------------
__global__ void k_detect(const int* __restrict__ ei32) {
    int v = ei32[2 * threadIdx.x + 1];
    int anynz = __syncthreads_or(v != 0);
    if (threadIdx.x == 0) g_is64 = (anynz == 0) ? 1 : 0;
}

__global__ void k_init() {
    int i = blockIdx.x * blockDim.x + threadIdx.x;
    int stride = gridDim.x * blockDim.x;
    for (int j = i; j < N_NODES; j += stride) { g_cur_src[j] = 0; g_cur_dst[j] = 0; }
    if (i == 0) {
        g_text[0] = fenc(-1e30f); g_text[1] = fenc(1e30f);
        g_text[2] = fenc(-1e30f); g_text[3] = fenc(1e30f);
    }
}

__global__ void k_hist(const int* __restrict__ ei32, const float* __restrict__ wm) {
    int i0 = blockIdx.x * blockDim.x + threadIdx.x;
    int stride = gridDim.x * blockDim.x;
    int is64 = g_is64;
    float tpmax = -1e30f, tpmin = 1e30f, tnmax = -1e30f, tnmin = 1e30f;
    for (int e = i0; e < N_EDGES; e += stride) {
        int s, d;
        load_edge(ei32, is64, e, s, d);
        atomicAdd(&g_cur_src[s], 1);
        atomicAdd(&g_cur_dst[d], 1);
        float t = wm[e];
        if (t >= 0.f) { tpmax = fmaxf(tpmax, t); tpmin = fminf(tpmin, t); }
        else          { tnmax = fmaxf(tnmax, t); tnmin = fminf(tnmin, t); }
    }
    for (int o = 16; o; o >>= 1) {
        tpmax = fmaxf(tpmax, __shfl_xor_sync(0xffffffffu, tpmax, o));
        tpmin = fminf(tpmin, __shfl_xor_sync(0xffffffffu, tpmin, o));
        tnmax = fmaxf(tnmax, __shfl_xor_sync(0xffffffffu, tnmax, o));
        tnmin = fminf(tnmin, __shfl_xor_sync(0xffffffffu, tnmin, o));
    }
    if ((threadIdx.x & 31) == 0) {
        atomicMax(&g_text[0], fenc(tpmax)); atomicMin(&g_text[1], fenc(tpmin));
        atomicMax(&g_text[2], fenc(tnmax)); atomicMin(&g_text[3], fenc(tnmin));
    }
}

// ---- multi-block exclusive scan over both histograms ----
__global__ void k_scan_part() {
    int arr = blockIdx.x / SCAN_BPA;
    int b   = blockIdx.x % SCAN_BPA;
    const int* cnt = arr ? g_cur_dst : g_cur_src;
    int idx = b * SCAN_TPB + threadIdx.x;
    int v = (idx < N_NODES) ? cnt[idx] : 0;
    // block reduce
    for (int o = 16; o; o >>= 1) v += __shfl_xor_sync(0xffffffffu, v, o);
    __shared__ int ws[SCAN_TPB / 32];
    int lane = threadIdx.x & 31, wid = threadIdx.x >> 5;
    if (lane == 0) ws[wid] = v;
    __syncthreads();
    if (wid == 0) {
        int s = (lane < SCAN_TPB / 32) ? ws[lane] : 0;
        for (int o = 16; o; o >>= 1) s += __shfl_xor_sync(0xffffffffu, s, o);
        if (lane == 0) g_part[blockIdx.x] = s;
    }
}

__global__ void k_scan_mid() {
    __shared__ int sm[SCAN_TPB];
    int tid = threadIdx.x;
    int v = (tid < SCAN_GRID) ? g_part[tid] : 0;
    sm[tid] = v;
    __syncthreads();
    for (int d = 1; d < SCAN_TPB; d <<= 1) {
        int t = (tid >= d) ? sm[tid - d] : 0;
        __syncthreads();
        sm[tid] += t;
        __syncthreads();
    }
    if (tid < SCAN_GRID) {
        int incl = sm[tid];
        int excl = incl - v;
        int base = (tid >= SCAN_BPA) ? sm[SCAN_BPA - 1] : 0;
        g_part[tid] = excl - base;
    }
}

__global__ void k_scan_final() {
    int arr = blockIdx.x / SCAN_BPA;
    int b   = blockIdx.x % SCAN_BPA;
    int* cnt = arr ? g_cur_dst : g_cur_src;
    int* off = arr ? g_off_dst : g_off_src;
    int tid = threadIdx.x;
    int idx = b * SCAN_TPB + tid;
    int v = (idx < N_NODES) ? cnt[idx] : 0;
    // block exclusive scan
    int lane = tid & 31, wid = tid >> 5;
    int inc = v;
    for (int o = 1; o < 32; o <<= 1) {
        int t = __shfl_up_sync(0xffffffffu, inc, o);
        if (lane >= o) inc += t;
    }
    __shared__ int ws[SCAN_TPB / 32];
    if (lane == 31) ws[wid] = inc;
    __syncthreads();
    if (wid == 0) {
        int s = (lane < SCAN_TPB / 32) ? ws[lane] : 0;
        for (int o = 1; o < SCAN_TPB / 32; o <<= 1) {
            int t = __shfl_up_sync(0xffffffffu, s, o);
            if (lane >= o) s += t;
        }
        if (lane < SCAN_TPB / 32) ws[lane] = s;
    }
    __syncthreads();
    int excl = inc - v + (wid ? ws[wid - 1] : 0) + g_part[blockIdx.x];
    if (idx < N_NODES) { off[idx] = excl; cnt[idx] = excl; }
    if (blockIdx.x == 0 && tid == 0) {
        g_off_src[N_NODES] = N_EDGES;
        g_off_dst[N_NODES] = N_EDGES;
    }
}

__global__ void k_scatter(const int* __restrict__ ei32, const float* __restrict__ wm) {
    int i0 = blockIdx.x * blockDim.x + threadIdx.x;
    int stride = gridDim.x * blockDim.x;
    int is64 = g_is64;
    for (int e = i0; e < N_EDGES; e += stride) {
        int s, d;
        load_edge(ei32, is64, e, s, d);
        float t = wm[e];
        int p = atomicAdd(&g_cur_src[s], 1);
        g_es_t[p] = t;
        int q = atomicAdd(&g_cur_dst[d], 1);
        g_ed_ts[q] = make_float2(t, __int_as_float(s));
    }
}

__global__ void k_transpose1(const float* __restrict__ W) {
    int idx = blockIdx.x * blockDim.x + threadIdx.x;
    if (idx < F_IN * HID) { int k = idx / F_IN, f = idx % F_IN; g_Wt1[f * HID + k] = W[idx]; }
}
__global__ void k_transpose2(const float* __restrict__ W) {
    int idx = blockIdx.x * blockDim.x + threadIdx.x;
    if (idx < HID * NCLS) { int k = idx / HID, f = idx % HID; g_Wt2[f * NCLS + k] = W[idx]; }
}

__device__ void prep_body(const float* __restrict__ w1, const float* __restrict__ w2,
                          int K, int Hd, float* Apos, float* Aneg, float* Mk) {
    int k = threadIdx.x;
    if (k >= K) return;
    float ap = 0.f, an = 0.f;
    for (int j = 0; j < Hd; j++) {
        float w = w1[j];
        float a = fmaxf(w, 0.2f * w);
        float b = fminf(w, 0.2f * w);
        float v = w2[k * Hd + j];
        ap = fmaf(a, v, ap);
        an = fmaf(b, v, an);
    }
    Apos[k] = ap; Aneg[k] = an;
    float tpmax = fdec(g_text[0]), tpmin = fdec(g_text[1]);
    float tnmax = fdec(g_text[2]), tnmin = fdec(g_text[3]);
    float m = -1e30f;
    if (tpmax > -1e29f) m = fmaxf(m, (ap >= 0.f ? tpmax : tpmin) * ap);
    if (tnmin <  1e29f) m = fmaxf(m, (an >= 0.f ? tnmax : tnmin) * an);
    if (m < -1e29f) m = 0.f;
    Mk[k] = m;
}
__global__ void k_prep1(const float* w1, const float* w2) { prep_body(w1, w2, HID, HID, g_Apos1, g_Aneg1, g_Mk1); }
__global__ void k_prep2(const float* w1, const float* w2) { prep_body(w1, w2, NCLS, NCLS, g_Apos2, g_Aneg2, g_Mk2); }

// ---------------- GEMM: out[n,k] = sum_i x[n,i] * W[k,i] + b[k] ----------------
// Each thread: 2 k-channels x 8 nodes = 16 accumulators.
// Per inner iter: 2x LDS.128 (group-broadcast) + 1x LDG.64 + 16 FMA.
template <int F, int K>
__device__ void gemm_body(const float* __restrict__ x, const float* __restrict__ Wt,
                          const float* __restrict__ bias, float* __restrict__ out) {
    const int KH  = K / 2;          // threads along k
    const int G   = 128 / KH;       // node groups per block
    const int NPB = 8;              // nodes per group
    const int NB  = G * NPB;        // nodes per block
    __shared__ __align__(16) float xs[NB * F];
    int tid = threadIdx.x;
    int node0 = blockIdx.x * NB;
    for (int idx = tid; idx < NB * F; idx += 128) {
        int nl = idx / F, i = idx % F;
        int node = node0 + nl;
        float v = (node < N_NODES) ? x[(size_t)node * F + i] : 0.f;
        int g2 = nl / NPB, j = nl % NPB;
        xs[(g2 * F + i) * NPB + j] = v;
    }
    __syncthreads();
    int k0 = (tid % KH) * 2, grp = tid / KH;
    const float4* xs4 = (const float4*)(xs) + (size_t)grp * F * 2;
    float acc0[8] = {0, 0, 0, 0, 0, 0, 0, 0};
    float acc1[8] = {0, 0, 0, 0, 0, 0, 0, 0};
#pragma unroll 4
    for (int i = 0; i < F; i++) {
        float2 w = *(const float2*)&Wt[i * K + k0];
        float4 a = xs4[2 * i], b = xs4[2 * i + 1];
        acc0[0] = fmaf(a.x, w.x, acc0[0]); acc1[0] = fmaf(a.x, w.y, acc1[0]);
        acc0[1] = fmaf(a.y, w.x, acc0[1]); acc1[1] = fmaf(a.y, w.y, acc1[1]);
        acc0[2] = fmaf(a.z, w.x, acc0[2]); acc1[2] = fmaf(a.z, w.y, acc1[2]);
        acc0[3] = fmaf(a.w, w.x, acc0[3]); acc1[3] = fmaf(a.w, w.y, acc1[3]);
        acc0[4] = fmaf(b.x, w.x, acc0[4]); acc1[4] = fmaf(b.x, w.y, acc1[4]);
        acc0[5] = fmaf(b.y, w.x, acc0[5]); acc1[5] = fmaf(b.y, w.y, acc1[5]);
        acc0[6] = fmaf(b.z, w.x, acc0[6]); acc1[6] = fmaf(b.z, w.y, acc1[6]);
        acc0[7] = fmaf(b.w, w.x, acc0[7]); acc1[7] = fmaf(b.w, w.y, acc1[7]);
    }
    float b0 = __ldg(&bias[k0]), b1 = __ldg(&bias[k0 + 1]);
#pragma unroll
    for (int j = 0; j < 8; j++) {
        int node = node0 + grp * NPB + j;
        if (node < N_NODES)
            *(float2*)&out[(size_t)node * K + k0] = make_float2(acc0[j] + b0, acc1[j] + b1);
    }
}
__global__ void k_gemm1(const float* __restrict__ x, const float* __restrict__ b) {
    gemm_body<F_IN, HID>(x, g_Wt1, b, g_x1);
}
__global__ void k_gemm2(const float* __restrict__ b) {
    gemm_body<HID, NCLS>(g_h1, g_Wt2, b, g_x2);
}

// ---------------- src pass: softmax denominator folded into y = x1/S ----------------
template <int K>
__device__ void kc_body(const float* __restrict__ x1, const float* __restrict__ Apos,
                        const float* __restrict__ Aneg, const float* __restrict__ Mk,
                        float* __restrict__ y) {
    const int NPB = 128 / K;
    int tid = threadIdx.x;
    int node = blockIdx.x * NPB + tid / K;
    int k = tid % K;
    if (node >= N_NODES) return;
    int a = g_off_src[node], b = g_off_src[node + 1];
    float Ap = Apos[k], An = Aneg[k], M = Mk[k];
    float S = 0.f;
    for (int e = a; e < b; e++) {
        float t = __ldg(&g_es_t[e]);
        float c = (t >= 0.f) ? Ap : An;
        S += __expf(fmaf(t, c, -M));
    }
    y[(size_t)node * K + k] = x1[(size_t)node * K + k] / (S + 1e-16f);
}
__global__ void k_kc1() { kc_body<HID>(g_x1, g_Apos1, g_Aneg1, g_Mk1, g_y1); }
__global__ void k_kc2() { kc_body<NCLS>(g_x2, g_Apos2, g_Aneg2, g_Mk2, g_y2); }

// ---------------- dst pass: out[v,k] = sum_{e: dst=v} exp(t*c_k - Mk) * y[src,k] ----------------
template <int K, int MODE>  // MODE 0: ELU, MODE 1: log_softmax over K=16 lanes
__device__ void kd_body(const float* __restrict__ y, const float* __restrict__ Apos,
                        const float* __restrict__ Aneg, const float* __restrict__ Mk,
                        float* __restrict__ out) {
    const int NPB = 128 / K;
    int tid = threadIdx.x;
    int node = blockIdx.x * NPB + tid / K;
    int k = tid % K;
    if (node >= N_NODES) return;
    int a = g_off_dst[node], b = g_off_dst[node + 1];
    float Ap = Apos[k], An = Aneg[k], M = Mk[k];
    float acc = 0.f;
    for (int e = a; e < b; e++) {
        float2 ts = __ldg(&g_ed_ts[e]);
        float t = ts.x;
        int s = __float_as_int(ts.y);
        float c = (t >= 0.f) ? Ap : An;
        float yv = __ldg(&y[(size_t)s * K + k]);
        acc = fmaf(__expf(fmaf(t, c, -M)), yv, acc);
    }
    if (MODE == 0) {
        out[(size_t)node * K + k] = (acc > 0.f) ? acc : expm1f(acc);
    } else {
        float m = acc;
        for (int o = 8; o; o >>= 1) m = fmaxf(m, __shfl_xor_sync(0xffffffffu, m, o, 16));
        float es = __expf(acc - m);
        float ssum = es;
        for (int o = 8; o; o >>= 1) ssum += __shfl_xor_sync(0xffffffffu, ssum, o, 16);
        out[(size_t)node * K + k] = acc - m - __logf(ssum);
    }
}
__global__ void k_kd1() { kd_body<HID, 0>(g_y1, g_Apos1, g_Aneg1, g_Mk1, g_h1); }
__global__ void k_kd2(float* __restrict__ out) { kd_body<NCLS, 1>(g_y2, g_Apos2, g_Aneg2, g_Mk2, out); }

// ---------------- launch ----------------
extern "C" void kernel_launch(void* const* d_in, const int* in_sizes, int n_in,
                              void* d_out, int out_size) {
    const float* x      = (const float*)d_in[0];
    const int*   ei32   = (const int*)d_in[1];   // int32 or int64 (detected on device)
    const float* wm     = (const float*)d_in[2];
    const float* lin1_w = (const float*)d_in[3];
    const float* lin1_b = (const float*)d_in[4];
    const float* m1w1   = (const float*)d_in[5];
    const float* m1w2   = (const float*)d_in[6];
    const float* lin2_w = (const float*)d_in[8];
    const float* lin2_b = (const float*)d_in[9];
    const float* m2w1   = (const float*)d_in[10];
    const float* m2w2   = (const float*)d_in[11];
    float* out = (float*)d_out;

    k_detect<<<1, 512>>>(ei32);
    k_init<<<400, 256>>>();
    k_hist<<<2048, 256>>>(ei32, wm);
    k_scan_part<<<SCAN_GRID, SCAN_TPB>>>();
    k_scan_mid<<<1, SCAN_TPB>>>();
    k_scan_final<<<SCAN_GRID, SCAN_TPB>>>();
    k_scatter<<<2048, 256>>>(ei32, wm);
    k_transpose1<<<(F_IN * HID + 255) / 256, 256>>>(lin1_w);
    k_transpose2<<<(HID * NCLS + 255) / 256, 256>>>(lin2_w);
    k_prep1<<<1, HID>>>(m1w1, m1w2);
    k_prep2<<<1, NCLS>>>(m2w1, m2w2);

    // layer 1
    k_gemm1<<<(N_NODES + 31) / 32, 128>>>(x, lin1_b);
    k_kc1<<<(N_NODES + 1) / 2, 128>>>();
    k_kd1<<<(N_NODES + 1) / 2, 128>>>();

    // layer 2
    k_gemm2<<<(N_NODES + 127) / 128, 128>>>(lin2_b);
    k_kc2<<<(N_NODES + 7) / 8, 128>>>();
    k_kd2<<<(N_NODES + 7) / 8, 128>>>(out);
}